// round 1
// baseline (speedup 1.0000x reference)
#include <cuda_runtime.h>
#include <cuda_bf16.h>

// ---------------------------------------------------------------------------
// YOLO post-process: decode 3 heads -> conf threshold -> per-image top-100
// (sorted desc, lower-index-first ties) -> greedy class-aware NMS.
//
// Inputs (metadata order):
//   d_in[0] out13   [B,255,13,13] f32
//   d_in[1] out26   [B,255,26,26] f32
//   d_in[2] out52   [B,255,52,52] f32
//   d_in[3] anchors [3,3,2]       f32
//   d_in[4] thresh  scalar        f32
// Output: f32, sel [B,100,6] flattened, then keep [B,100] as 0/1 floats.
// ---------------------------------------------------------------------------

#define BMAX 32
#define KNMS 100
#define NBOX 10647           // (169+676+2704)*3
#define N1   507             // 13*13*3
#define N12  2535            // N1 + 26*26*3
#define TPB1 1024
#define ELEMS 11             // ceil(10647/1024)
#define CANDCAP 2048

__device__ int   g_topk_idx[BMAX * KNMS];
__device__ float g_topk_score[BMAX * KNMS];

// map global box index n -> (base plane ptr for this batch, SS, S, scale, a, cell)
__device__ __forceinline__ void map_box(
    int n, int b,
    const float* o13, const float* o26, const float* o52,
    const float** base, int* SS, int* S, int* scale, int* a, int* cell)
{
    int nl;
    if (n < N1)       { *base = o13 + (size_t)b * 255 * 169;  *SS = 169;  *S = 13; *scale = 0; nl = n; }
    else if (n < N12) { *base = o26 + (size_t)b * 255 * 676;  *SS = 676;  *S = 26; *scale = 1; nl = n - N1; }
    else              { *base = o52 + (size_t)b * 255 * 2704; *SS = 2704; *S = 52; *scale = 2; nl = n - N12; }
    *a = nl % 3;
    *cell = nl / 3;
}

__device__ __forceinline__ float box_score(
    int n, int b, const float* o13, const float* o26, const float* o52, float th)
{
    const float* base; int SS, S, scale, a, cell;
    map_box(n, b, o13, o26, o52, &base, &SS, &S, &scale, &a, &cell);
    float lg = base[(size_t)(a * 85) * SS + cell];
    float conf = 1.f / (1.f + expf(-lg));
    return (conf > th) ? conf : 0.f;
}

// ---------------------------------------------------------------------------
// Kernel 1: per-batch conf scores + histogram-based exact top-100 select.
// ---------------------------------------------------------------------------
__global__ __launch_bounds__(TPB1)
void score_topk_kernel(const float* __restrict__ o13,
                       const float* __restrict__ o26,
                       const float* __restrict__ o52,
                       const float* __restrict__ thresh_p)
{
    __shared__ unsigned int hist[130];
    __shared__ unsigned long long cand[CANDCAP];
    __shared__ unsigned int ncand_s;
    __shared__ int bt_s;
    __shared__ unsigned int validtot_s;

    const int b = blockIdx.x;
    const int tid = threadIdx.x;
    const float th = *thresh_p;

    if (tid < 130) hist[tid] = 0u;
    if (tid == 0) ncand_s = 0u;
    __syncthreads();

    float sc[ELEMS];
    int   bins[ELEMS];

#pragma unroll
    for (int j = 0; j < ELEMS; j++) {
        int n = tid + j * TPB1;
        float s = 0.f;
        int bin = -1;
        if (n < NBOX) {
            s = box_score(n, b, o13, o26, o52, th);
            bin = 0;
            if (s > 0.f) {
                unsigned int k16 = __float_as_uint(s) >> 16;
                int bb = (int)k16 - 0x3F00 + 1;
                bin = bb < 1 ? 1 : (bb > 128 ? 128 : bb);
                atomicAdd(&hist[bin], 1u);
            }
        }
        sc[j] = s;
        bins[j] = bin;
    }
    __syncthreads();

    if (tid == 0) {
        unsigned int cum = 0; int bt = 1;
        for (int bb = 128; bb >= 1; bb--) {
            cum += hist[bb];
            if (cum >= KNMS) { bt = bb; break; }
        }
        bt_s = bt;
        validtot_s = cum;   // if cum<K, this is total valid count
    }
    __syncthreads();

    const int bt = bt_s;

    // compact candidates (all valid boxes with bin >= bt)
#pragma unroll
    for (int j = 0; j < ELEMS; j++) {
        if (bins[j] >= bt && bins[j] >= 1) {
            unsigned int pos = atomicAdd(&ncand_s, 1u);
            if (pos < CANDCAP) {
                int n = tid + j * TPB1;
                cand[pos] = ((unsigned long long)__float_as_uint(sc[j]) << 32)
                          | (unsigned long long)(0xFFFFFFFFu - (unsigned)n);
            }
        }
    }
    __syncthreads();

    unsigned int nc = ncand_s; if (nc > CANDCAP) nc = CANDCAP;

    // exact rank selection: rank = #keys strictly greater (keys unique via index)
    for (unsigned int c = tid; c < nc; c += TPB1) {
        unsigned long long kc = cand[c];
        int rank = 0;
        for (unsigned int j2 = 0; j2 < nc; j2++)
            rank += (cand[j2] > kc) ? 1 : 0;
        if (rank < KNMS) {
            int n = (int)(0xFFFFFFFFu - (unsigned)(kc & 0xFFFFFFFFull));
            g_topk_idx[b * KNMS + rank]   = n;
            g_topk_score[b * KNMS + rank] = __uint_as_float((unsigned)(kc >> 32));
        }
    }
    __syncthreads();

    // fallback: fewer than K valid boxes -> fill with zero-score boxes in index order
    if ((int)nc < KNMS && tid == 0) {
        int filled = (int)nc;
        for (int n = 0; n < NBOX && filled < KNMS; n++) {
            float s = box_score(n, b, o13, o26, o52, th);
            if (s == 0.f) {
                g_topk_idx[b * KNMS + filled] = n;
                g_topk_score[b * KNMS + filled] = 0.f;
                filled++;
            }
        }
    }
}

// ---------------------------------------------------------------------------
// Kernel 2: decode the selected boxes. One warp per (batch,k).
// ---------------------------------------------------------------------------
__global__ void decode_sel_kernel(const float* __restrict__ o13,
                                  const float* __restrict__ o26,
                                  const float* __restrict__ o52,
                                  const float* __restrict__ anchors,
                                  float* __restrict__ out, int total)
{
    int gw = (blockIdx.x * blockDim.x + threadIdx.x) >> 5;
    int lane = threadIdx.x & 31;
    if (gw >= total) return;
    int b = gw / KNMS, k = gw % KNMS;
    int n = g_topk_idx[b * KNMS + k];

    const float* base; int SS, S, scale, a, cell;
    map_box(n, b, o13, o26, o52, &base, &SS, &S, &scale, &a, &cell);
    const float* p = base + (size_t)(a * 85) * SS + cell;
    float stridef = (scale == 0) ? 32.f : (scale == 1 ? 16.f : 8.f);
    int y = cell / S, x = cell % S;

    // head fields (lanes 0..4), broadcast
    float f = (lane < 5) ? p[(size_t)lane * SS] : 0.f;
    float f0 = __shfl_sync(0xFFFFFFFFu, f, 0);
    float f1 = __shfl_sync(0xFFFFFFFFu, f, 1);
    float f2 = __shfl_sync(0xFFFFFFFFu, f, 2);
    float f3 = __shfl_sync(0xFFFFFFFFu, f, 3);
    float f4 = __shfl_sync(0xFFFFFFFFu, f, 4);

    // class argmax over 80 logits, first-max (lowest index) on ties
    unsigned long long best = 0ull;
#pragma unroll
    for (int c = lane; c < 80; c += 32) {
        float v = p[(size_t)(5 + c) * SS];
        unsigned u = __float_as_uint(v);
        u = (u & 0x80000000u) ? ~u : (u | 0x80000000u);   // order-preserving map
        unsigned long long key = ((unsigned long long)u << 32)
                               | (unsigned long long)(127u - (unsigned)c);
        if (key > best) best = key;
    }
#pragma unroll
    for (int off = 16; off; off >>= 1) {
        unsigned long long o2 = __shfl_xor_sync(0xFFFFFFFFu, best, off);
        if (o2 > best) best = o2;
    }
    int cls = 127 - (int)(best & 0xFFFFFFFFull);

    if (lane == 0) {
        float conf = 1.f / (1.f + expf(-f0));
        float sx   = 1.f / (1.f + expf(-f1));
        float sy   = 1.f / (1.f + expf(-f2));
        float ox = ((float)x + sx) * stridef;
        float oy = ((float)y + sy) * stridef;
        float w  = expf(f3) * anchors[scale * 6 + a * 2 + 0];
        float h  = expf(f4) * anchors[scale * 6 + a * 2 + 1];
        float* o = out + (size_t)(b * KNMS + k) * 6;
        o[0] = ox - w * 0.5f;
        o[1] = oy - h * 0.5f;
        o[2] = ox + w * 0.5f;
        o[3] = oy + h * 0.5f;
        o[4] = (float)cls;
        o[5] = conf;
    }
}

// ---------------------------------------------------------------------------
// Kernel 3: greedy per-class NMS, one block per batch (matches fori_loop ref).
// ---------------------------------------------------------------------------
__global__ void nms_kernel(float* __restrict__ out, int B)
{
    __shared__ float x1s[KNMS], y1s[KNMS], x2s[KNMS], y2s[KNMS], cls[KNMS], ar[KNMS];
    __shared__ int keep[KNMS];

    int b = blockIdx.x;
    int tid = threadIdx.x;

    if (tid < KNMS) {
        const float* r = out + (size_t)(b * KNMS + tid) * 6;
        float a0 = r[0], a1 = r[1], a2 = r[2], a3 = r[3];
        x1s[tid] = a0; y1s[tid] = a1; x2s[tid] = a2; y2s[tid] = a3;
        cls[tid] = r[4];
        ar[tid]  = fmaxf(a2 - a0, 0.f) * fmaxf(a3 - a1, 0.f);
        keep[tid] = (g_topk_score[b * KNMS + tid] > 0.f) ? 1 : 0;
    }
    __syncthreads();

    for (int i = 0; i < KNMS; i++) {
        if (keep[i]) {
            int j = tid;
            if (j < KNMS && j > i && cls[j] == cls[i]) {
                float xx1 = fmaxf(x1s[i], x1s[j]);
                float yy1 = fmaxf(y1s[i], y1s[j]);
                float xx2 = fminf(x2s[i], x2s[j]);
                float yy2 = fminf(y2s[i], y2s[j]);
                float inter = fmaxf(xx2 - xx1, 0.f) * fmaxf(yy2 - yy1, 0.f);
                float uni = ar[i] + ar[j] - inter;
                float iou = inter / fmaxf(uni, 1e-9f);
                if (iou > 0.3f) keep[j] = 0;
            }
        }
        __syncthreads();
    }

    if (tid < KNMS)
        out[(size_t)B * KNMS * 6 + b * KNMS + tid] = keep[tid] ? 1.f : 0.f;
}

// ---------------------------------------------------------------------------
extern "C" void kernel_launch(void* const* d_in, const int* in_sizes, int n_in,
                              void* d_out, int out_size)
{
    const float* o13     = (const float*)d_in[0];
    const float* o26     = (const float*)d_in[1];
    const float* o52     = (const float*)d_in[2];
    const float* anchors = (const float*)d_in[3];
    const float* thresh  = (const float*)d_in[4];
    float* out = (float*)d_out;

    int B = in_sizes[0] / (255 * 169);
    if (B > BMAX) B = BMAX;

    score_topk_kernel<<<B, TPB1>>>(o13, o26, o52, thresh);

    int totalWarps = B * KNMS;
    int threads = 256;
    int blocks = (totalWarps * 32 + threads - 1) / threads;
    decode_sel_kernel<<<blocks, threads>>>(o13, o26, o52, anchors, out, totalWarps);

    nms_kernel<<<B, 128>>>(out, B);
}